// round 1
// baseline (speedup 1.0000x reference)
#include <cuda_runtime.h>
#include <math.h>

// Shapes (fixed by the problem)
#define B_  8
#define Q_  512
#define D_  4096
#define H_  1024

#define BM 128
#define BN 128
#define BK 16
#define TM 8
#define TN 8
// 256 threads: 16x16 layout, each computes 8x8

// Scratch for projected queries: [B*Q, H] = 4096*1024 floats = 16 MB
__device__ float g_q[(long long)B_ * Q_ * H_];

// C[M,N] = alpha * A[M,K] * op(B) (+ bias[n]); op(B) = B[K,N] (NN) or B[N,K]^T (NT)
template <bool TRANS_B, bool HAS_BIAS>
__global__ void __launch_bounds__(256, 2) sgemm_kernel(
    const float* __restrict__ A, const float* __restrict__ Bm,
    float* __restrict__ C, const float* __restrict__ bias,
    int M, int N, int K, float alpha,
    long long strideA, long long strideB, long long strideC)
{
    const int batch = blockIdx.z;
    A  += (long long)batch * strideA;
    Bm += (long long)batch * strideB;
    C  += (long long)batch * strideC;

    __shared__ float As[BK][BM + 4];
    __shared__ float Bs[BK][BN + 4];

    const int bm = blockIdx.y * BM;
    const int bn = blockIdx.x * BN;
    const int tid = threadIdx.x;
    const int tx = tid & 15;       // 0..15 -> col group
    const int ty = tid >> 4;       // 0..15 -> row group

    float acc[TM][TN];
#pragma unroll
    for (int i = 0; i < TM; i++)
#pragma unroll
        for (int j = 0; j < TN; j++) acc[i][j] = 0.0f;

    for (int kb = 0; kb < K; kb += BK) {
        // ---- load A tile (BM x BK), store transposed As[k][m] ----
#pragma unroll
        for (int r = 0; r < 2; r++) {
            int f = tid + r * 256;          // 0..511 float4 slots
            int row = f >> 2;               // 0..127
            int kq  = (f & 3) * 4;          // 0,4,8,12
            float4 v = *(const float4*)(A + (long long)(bm + row) * K + kb + kq);
            As[kq + 0][row] = v.x;
            As[kq + 1][row] = v.y;
            As[kq + 2][row] = v.z;
            As[kq + 3][row] = v.w;
        }
        // ---- load B tile into Bs[k][n] ----
        if (TRANS_B) {
            // B is [N,K] row-major; read 4 consecutive k per thread
#pragma unroll
            for (int r = 0; r < 2; r++) {
                int f = tid + r * 256;
                int nrow = f >> 2;          // 0..127
                int kq   = (f & 3) * 4;
                float4 v = *(const float4*)(Bm + (long long)(bn + nrow) * K + kb + kq);
                Bs[kq + 0][nrow] = v.x;
                Bs[kq + 1][nrow] = v.y;
                Bs[kq + 2][nrow] = v.z;
                Bs[kq + 3][nrow] = v.w;
            }
        } else {
            // B is [K,N] row-major; direct vector copy
#pragma unroll
            for (int r = 0; r < 2; r++) {
                int f = tid + r * 256;
                int krow = f >> 5;          // 0..15
                int col  = (f & 31) * 4;    // 0..124
                float4 v = *(const float4*)(Bm + (long long)(kb + krow) * N + bn + col);
                *(float4*)&Bs[krow][col] = v;
            }
        }
        __syncthreads();

#pragma unroll
        for (int k = 0; k < BK; k++) {
            float4 a0 = *(const float4*)&As[k][ty * TM];
            float4 a1 = *(const float4*)&As[k][ty * TM + 4];
            float4 b0 = *(const float4*)&Bs[k][tx * TN];
            float4 b1 = *(const float4*)&Bs[k][tx * TN + 4];
            float a[TM] = {a0.x, a0.y, a0.z, a0.w, a1.x, a1.y, a1.z, a1.w};
            float b[TN] = {b0.x, b0.y, b0.z, b0.w, b1.x, b1.y, b1.z, b1.w};
#pragma unroll
            for (int i = 0; i < TM; i++)
#pragma unroll
                for (int j = 0; j < TN; j++)
                    acc[i][j] = fmaf(a[i], b[j], acc[i][j]);
        }
        __syncthreads();
    }

    // ---- epilogue ----
#pragma unroll
    for (int i = 0; i < TM; i++) {
        int row = bm + ty * TM + i;
        float* crow = C + (long long)row * N + bn + tx * TN;
#pragma unroll
        for (int j4 = 0; j4 < 2; j4++) {
            float4 v;
            v.x = acc[i][j4 * 4 + 0] * alpha;
            v.y = acc[i][j4 * 4 + 1] * alpha;
            v.z = acc[i][j4 * 4 + 2] * alpha;
            v.w = acc[i][j4 * 4 + 3] * alpha;
            if (HAS_BIAS) {
                int col = bn + tx * TN + j4 * 4;
                v.x += bias[col + 0];
                v.y += bias[col + 1];
                v.z += bias[col + 2];
                v.w += bias[col + 3];
            }
            *(float4*)(crow + j4 * 4) = v;
        }
    }
}

// In-place masked softmax over rows of length D_. One block per (b,q) row.
__global__ void __launch_bounds__(256) softmax_kernel(
    float* __restrict__ attn, const int* __restrict__ mask)
{
    const int row = blockIdx.x;            // b*Q_ + q
    const int b = row / Q_;
    const int* mrow = mask + (long long)b * D_;
    float* s = attn + (long long)row * D_;
    const int tid = threadIdx.x;

    float v[16];
    int   mk[16];
    float mx = -INFINITY;
#pragma unroll
    for (int i = 0; i < 16; i++) {
        int d = tid + i * 256;
        mk[i] = mrow[d];
        float x = s[d];
        v[i] = (mk[i] != 0) ? x : -INFINITY;
        mx = fmaxf(mx, v[i]);
    }

    __shared__ float red[8];
    // warp reduce max
#pragma unroll
    for (int off = 16; off > 0; off >>= 1)
        mx = fmaxf(mx, __shfl_xor_sync(0xffffffffu, mx, off));
    if ((tid & 31) == 0) red[tid >> 5] = mx;
    __syncthreads();
    if (tid < 32) {
        float m2 = (tid < 8) ? red[tid] : -INFINITY;
#pragma unroll
        for (int off = 4; off > 0; off >>= 1)
            m2 = fmaxf(m2, __shfl_xor_sync(0xffffffffu, m2, off));
        if (tid == 0) red[0] = m2;
    }
    __syncthreads();
    mx = red[0];

    float sum = 0.0f;
#pragma unroll
    for (int i = 0; i < 16; i++) {
        float e = (mk[i] != 0) ? expf(v[i] - mx) : 0.0f;
        v[i] = e;
        sum += e;
    }
#pragma unroll
    for (int off = 16; off > 0; off >>= 1)
        sum += __shfl_xor_sync(0xffffffffu, sum, off);
    __syncthreads();
    if ((tid & 31) == 0) red[tid >> 5] = sum;
    __syncthreads();
    if (tid < 32) {
        float s2 = (tid < 8) ? red[tid] : 0.0f;
#pragma unroll
        for (int off = 4; off > 0; off >>= 1)
            s2 += __shfl_xor_sync(0xffffffffu, s2, off);
        if (tid == 0) red[0] = s2;
    }
    __syncthreads();
    const float inv = 1.0f / red[0];

#pragma unroll
    for (int i = 0; i < 16; i++) {
        int d = tid + i * 256;
        s[d] = v[i] * inv;
    }
}

extern "C" void kernel_launch(void* const* d_in, const int* in_sizes, int n_in,
                              void* d_out, int out_size)
{
    const float* query = (const float*)d_in[0];   // [B,Q,H]
    const float* doc   = (const float*)d_in[1];   // [B,D,H]
    const int*   mask  = (const int*)d_in[2];     // [B,D]
    const float* W     = (const float*)d_in[3];   // [H,H]
    const float* bias  = (const float*)d_in[4];   // [H]

    float* out = (float*)d_out;
    float* retrieved = out;                                    // [B,Q,H]
    float* attn = out + (long long)B_ * Q_ * H_;               // [B,Q,D]

    float* qproj = nullptr;
    cudaGetSymbolAddress((void**)&qproj, g_q);

    dim3 threads(256);
    const float scale = 1.0f / 32.0f;   // 1/sqrt(H)

    // 1) q = query @ W + bias   (M=B*Q=4096, N=H, K=H), single batch
    {
        dim3 grid(H_ / BN, (B_ * Q_) / BM, 1);
        sgemm_kernel<false, true><<<grid, threads>>>(
            query, W, qproj, bias, B_ * Q_, H_, H_, 1.0f, 0, 0, 0);
    }
    // 2) scores = q @ doc^T * scale  -> attn region  (batched NT)
    {
        dim3 grid(D_ / BN, Q_ / BM, B_);
        sgemm_kernel<true, false><<<grid, threads>>>(
            qproj, doc, attn, nullptr, Q_, D_, H_, scale,
            (long long)Q_ * H_, (long long)D_ * H_, (long long)Q_ * D_);
    }
    // 3) masked softmax in place over D
    {
        softmax_kernel<<<B_ * Q_, threads>>>(attn, mask);
    }
    // 4) retrieved = attn @ doc  (batched NN)
    {
        dim3 grid(H_ / BN, Q_ / BM, B_);
        sgemm_kernel<false, false><<<grid, threads>>>(
            attn, doc, retrieved, nullptr, Q_, H_, D_, 1.0f,
            (long long)Q_ * D_, (long long)D_ * H_, (long long)Q_ * H_);
    }
}

// round 3
// speedup vs baseline: 2.6463x; 2.6463x over previous
#include <cuda_runtime.h>
#include <math.h>
#include <stdint.h>

#define B_  8
#define Q_  512
#define D_  4096
#define H_  1024

#define STAGES 4
#define TILE   128
#define BK     16
#define STRD   20                       // smem row stride in floats (bank-safe)
#define STAGE_FLOATS (2 * TILE * STRD)  // A tile + B tile = 5120 floats / stage

// ---------------- scratch (static device memory; no allocs allowed) ----------
__device__ float g_q[(size_t)B_ * Q_ * H_];        // projected queries, tf32-RN
__device__ float g_query[(size_t)B_ * Q_ * H_];    // RN(query)
__device__ float g_WT[(size_t)H_ * H_];            // RN(W^T)
__device__ float g_doc[(size_t)B_ * D_ * H_];      // RN(doc)   [B,D,H]
__device__ float g_docT[(size_t)B_ * H_ * D_];     // RN(doc^T) [B,H,D]
__device__ float g_attn[(size_t)B_ * Q_ * D_];     // RN(attn)  [B,Q,D]

// ---------------- helpers ------------------------------------------------
__device__ __forceinline__ float tf32_rn(float x) {
    float r; asm("cvt.rna.tf32.f32 %0, %1;" : "=f"(r) : "f"(x)); return r;
}
__device__ __forceinline__ void cp_async16(uint32_t dst, const void* src) {
    asm volatile("cp.async.cg.shared.global [%0], [%1], 16;" :: "r"(dst), "l"(src));
}
#define CP_COMMIT() asm volatile("cp.async.commit_group;" ::: "memory")
#define CP_WAIT(n)  asm volatile("cp.async.wait_group %0;" :: "n"(n) : "memory")

__device__ __forceinline__ uint32_t smem_u32(const void* p) {
    uint32_t a;
    asm("{ .reg .u64 t; cvta.to.shared.u64 t, %1; cvt.u32.u64 %0, t; }" : "=r"(a) : "l"(p));
    return a;
}

__device__ __forceinline__ void mma_tf32(float* c, const uint32_t* a, const uint32_t* b) {
    asm volatile(
        "mma.sync.aligned.m16n8k8.row.col.f32.tf32.tf32.f32 "
        "{%0,%1,%2,%3}, {%4,%5,%6,%7}, {%8,%9}, {%0,%1,%2,%3};"
        : "+f"(c[0]), "+f"(c[1]), "+f"(c[2]), "+f"(c[3])
        : "r"(a[0]), "r"(a[1]), "r"(a[2]), "r"(a[3]), "r"(b[0]), "r"(b[1]));
}

// ---------------- warp-MMA TF32 GEMM -----------------------------------------
// C[m][n] = alpha * sum_k A[m][k] * B[n][k] (+ bias[n]); A,B K-major pitch K.
// grid: (N/128, M/128, batches), 256 threads.
template <bool HAS_BIAS, bool CVT_OUT>
__global__ void __launch_bounds__(256, 1) wgemm128(
    const float* __restrict__ A, const float* __restrict__ Bm,
    float* __restrict__ C, const float* __restrict__ bias,
    int K, int ldc, float alpha,
    size_t strideA, size_t strideB, size_t strideC)
{
    extern __shared__ float smf[];
    const uint32_t sbase = smem_u32(smf);

    const int tid  = threadIdx.x;
    const int lane = tid & 31;
    const int wid  = tid >> 5;
    const int row  = lane >> 2;      // 0..7
    const int tig  = lane & 3;       // 0..3
    const int warp_m = (wid & 3) * 32;
    const int warp_n = (wid >> 2) * 64;

    const size_t batch = blockIdx.z;
    const float* Ab = A + batch * strideA + (size_t)(blockIdx.y * TILE) * K;
    const float* Bb = Bm + batch * strideB + (size_t)(blockIdx.x * TILE) * K;

    // per-thread cp.async slots: 2 chunks for A, 2 for B
    const int c0 = tid, c1 = tid + 256;          // 0..511
    const int ar0 = c0 >> 2, aq0 = c0 & 3;
    const int ar1 = c1 >> 2, aq1 = c1 & 3;

    float acc[2][8][4];
#pragma unroll
    for (int mt = 0; mt < 2; mt++)
#pragma unroll
        for (int nt = 0; nt < 8; nt++)
#pragma unroll
            for (int i = 0; i < 4; i++) acc[mt][nt][i] = 0.0f;

    const int NK = K / BK;

    // ---- prologue: fill STAGES-1 stages ----
#pragma unroll
    for (int s = 0; s < STAGES - 1; s++) {
        const uint32_t stA = sbase + s * STAGE_FLOATS * 4;
        const uint32_t stB = stA + TILE * STRD * 4;
        const float* gA = Ab + s * BK;
        const float* gB = Bb + s * BK;
        cp_async16(stA + (ar0 * STRD + aq0 * 4) * 4, gA + (size_t)ar0 * K + aq0 * 4);
        cp_async16(stA + (ar1 * STRD + aq1 * 4) * 4, gA + (size_t)ar1 * K + aq1 * 4);
        cp_async16(stB + (ar0 * STRD + aq0 * 4) * 4, gB + (size_t)ar0 * K + aq0 * 4);
        cp_async16(stB + (ar1 * STRD + aq1 * 4) * 4, gB + (size_t)ar1 * K + aq1 * 4);
        CP_COMMIT();
    }

    for (int kb = 0; kb < NK; kb++) {
        CP_WAIT(STAGES - 2);
        __syncthreads();

        // issue next stage load (overwrites stage consumed 1 iter ago)
        const int kn = kb + STAGES - 1;
        if (kn < NK) {
            const int s = kn % STAGES;
            const uint32_t stA = sbase + s * STAGE_FLOATS * 4;
            const uint32_t stB = stA + TILE * STRD * 4;
            const float* gA = Ab + kn * BK;
            const float* gB = Bb + kn * BK;
            cp_async16(stA + (ar0 * STRD + aq0 * 4) * 4, gA + (size_t)ar0 * K + aq0 * 4);
            cp_async16(stA + (ar1 * STRD + aq1 * 4) * 4, gA + (size_t)ar1 * K + aq1 * 4);
            cp_async16(stB + (ar0 * STRD + aq0 * 4) * 4, gB + (size_t)ar0 * K + aq0 * 4);
            cp_async16(stB + (ar1 * STRD + aq1 * 4) * 4, gB + (size_t)ar1 * K + aq1 * 4);
        }
        CP_COMMIT();

        // ---- compute current stage ----
        const float* As = smf + (kb % STAGES) * STAGE_FLOATS;
        const float* Bs = As + TILE * STRD;
#pragma unroll
        for (int kk = 0; kk < BK; kk += 8) {
            uint32_t a[2][4], b[8][2];
#pragma unroll
            for (int mt = 0; mt < 2; mt++) {
                const uint32_t* ap = (const uint32_t*)(As + (warp_m + mt * 16 + row) * STRD + kk + tig);
                a[mt][0] = ap[0];
                a[mt][1] = ap[8 * STRD];
                a[mt][2] = ap[4];
                a[mt][3] = ap[8 * STRD + 4];
            }
#pragma unroll
            for (int nt = 0; nt < 8; nt++) {
                const uint32_t* bp = (const uint32_t*)(Bs + (warp_n + nt * 8 + row) * STRD + kk + tig);
                b[nt][0] = bp[0];
                b[nt][1] = bp[4];
            }
#pragma unroll
            for (int mt = 0; mt < 2; mt++)
#pragma unroll
                for (int nt = 0; nt < 8; nt++)
                    mma_tf32(acc[mt][nt], a[mt], b[nt]);
        }
        __syncthreads();
    }

    // ---- epilogue ----
    float* Cb = C + batch * strideC;
#pragma unroll
    for (int mt = 0; mt < 2; mt++) {
        const int r0 = blockIdx.y * TILE + warp_m + mt * 16 + row;
#pragma unroll
        for (int nt = 0; nt < 8; nt++) {
            const int col = blockIdx.x * TILE + warp_n + nt * 8 + 2 * tig;
            float bx = 0.f, by = 0.f;
            if (HAS_BIAS) { bx = __ldg(bias + col); by = __ldg(bias + col + 1); }
            float2 v0, v1;
            v0.x = acc[mt][nt][0] * alpha + bx;
            v0.y = acc[mt][nt][1] * alpha + by;
            v1.x = acc[mt][nt][2] * alpha + bx;
            v1.y = acc[mt][nt][3] * alpha + by;
            if (CVT_OUT) {
                v0.x = tf32_rn(v0.x); v0.y = tf32_rn(v0.y);
                v1.x = tf32_rn(v1.x); v1.y = tf32_rn(v1.y);
            }
            *(float2*)(Cb + (size_t)r0 * ldc + col) = v0;
            *(float2*)(Cb + (size_t)(r0 + 8) * ldc + col) = v1;
        }
    }
}

// ---------------- prep kernels ----------------------------------------------
__global__ void k_prep_q(const float* __restrict__ q) {
    size_t i = (size_t)blockIdx.x * blockDim.x + threadIdx.x;
    float4 v = ((const float4*)q)[i];
    v.x = tf32_rn(v.x); v.y = tf32_rn(v.y); v.z = tf32_rn(v.z); v.w = tf32_rn(v.w);
    ((float4*)g_query)[i] = v;
}

__global__ void k_prep_W(const float* __restrict__ W) {
    __shared__ float t[32][33];
    const int bx = blockIdx.x * 32;   // n
    const int by = blockIdx.y * 32;   // k
    const int x = threadIdx.x, y = threadIdx.y;
#pragma unroll
    for (int r = 0; r < 4; r++)
        t[y + 8 * r][x] = tf32_rn(W[(size_t)(by + y + 8 * r) * H_ + bx + x]);
    __syncthreads();
#pragma unroll
    for (int r = 0; r < 4; r++)
        g_WT[(size_t)(bx + y + 8 * r) * H_ + by + x] = t[x][y + 8 * r];
}

__global__ void k_prep_doc(const float* __restrict__ doc) {
    __shared__ float t[32][33];
    const size_t b = blockIdx.z;
    const float* Db = doc + b * (size_t)D_ * H_;
    float* Gd = g_doc + b * (size_t)D_ * H_;
    float* Gt = g_docT + b * (size_t)H_ * D_;
    const int bx = blockIdx.x * 32;   // h
    const int by = blockIdx.y * 32;   // d
    const int x = threadIdx.x, y = threadIdx.y;
#pragma unroll
    for (int r = 0; r < 4; r++) {
        int row = y + 8 * r;
        float v = tf32_rn(Db[(size_t)(by + row) * H_ + bx + x]);
        Gd[(size_t)(by + row) * H_ + bx + x] = v;
        t[row][x] = v;
    }
    __syncthreads();
#pragma unroll
    for (int r = 0; r < 4; r++)
        Gt[(size_t)(bx + y + 8 * r) * D_ + by + x] = t[x][y + 8 * r];
}

// ---------------- masked softmax over D, writes fp32 + tf32 copies -----------
__global__ void __launch_bounds__(256) softmax_kernel(
    float* __restrict__ attn, const int* __restrict__ mask)
{
    const int row = blockIdx.x;            // b*Q_ + q
    const int b = row / Q_;
    const int* mrow = mask + (size_t)b * D_;
    float* s = attn + (size_t)row * D_;
    float* s32 = g_attn + (size_t)row * D_;
    const int tid = threadIdx.x;

    float v[16];
    int mk[16];
    float mx = -INFINITY;
#pragma unroll
    for (int i = 0; i < 16; i++) {
        int d = tid + i * 256;
        mk[i] = mrow[d];
        float x = s[d];
        v[i] = (mk[i] != 0) ? x : -INFINITY;
        mx = fmaxf(mx, v[i]);
    }

    __shared__ float red[8];
#pragma unroll
    for (int off = 16; off > 0; off >>= 1)
        mx = fmaxf(mx, __shfl_xor_sync(0xffffffffu, mx, off));
    if ((tid & 31) == 0) red[tid >> 5] = mx;
    __syncthreads();
    if (tid < 32) {
        float m2 = (tid < 8) ? red[tid] : -INFINITY;
#pragma unroll
        for (int off = 4; off > 0; off >>= 1)
            m2 = fmaxf(m2, __shfl_xor_sync(0xffffffffu, m2, off));
        if (tid == 0) red[0] = m2;
    }
    __syncthreads();
    mx = red[0];

    float sum = 0.0f;
#pragma unroll
    for (int i = 0; i < 16; i++) {
        float e = (mk[i] != 0) ? expf(v[i] - mx) : 0.0f;
        v[i] = e;
        sum += e;
    }
#pragma unroll
    for (int off = 16; off > 0; off >>= 1)
        sum += __shfl_xor_sync(0xffffffffu, sum, off);
    __syncthreads();
    if ((tid & 31) == 0) red[tid >> 5] = sum;
    __syncthreads();
    if (tid < 32) {
        float s2 = (tid < 8) ? red[tid] : 0.0f;
#pragma unroll
        for (int off = 4; off > 0; off >>= 1)
            s2 += __shfl_xor_sync(0xffffffffu, s2, off);
        if (tid == 0) red[0] = s2;
    }
    __syncthreads();
    const float inv = 1.0f / red[0];

#pragma unroll
    for (int i = 0; i < 16; i++) {
        int d = tid + i * 256;
        float w = v[i] * inv;
        s[d] = w;
        s32[d] = tf32_rn(w);
    }
}

// ---------------- launch -----------------------------------------------------
extern "C" void kernel_launch(void* const* d_in, const int* in_sizes, int n_in,
                              void* d_out, int out_size)
{
    const float* query = (const float*)d_in[0];   // [B,Q,H]
    const float* doc   = (const float*)d_in[1];   // [B,D,H]
    const int*   mask  = (const int*)d_in[2];     // [B,D]
    const float* W     = (const float*)d_in[3];   // [H,H]
    const float* bias  = (const float*)d_in[4];   // [H]

    float* out = (float*)d_out;
    float* retrieved = out;                               // [B,Q,H]
    float* attn = out + (size_t)B_ * Q_ * H_;             // [B,Q,D]

    float *p_q, *p_query, *p_WT, *p_doc, *p_docT, *p_attn;
    cudaGetSymbolAddress((void**)&p_q, g_q);
    cudaGetSymbolAddress((void**)&p_query, g_query);
    cudaGetSymbolAddress((void**)&p_WT, g_WT);
    cudaGetSymbolAddress((void**)&p_doc, g_doc);
    cudaGetSymbolAddress((void**)&p_docT, g_docT);
    cudaGetSymbolAddress((void**)&p_attn, g_attn);

    const int smem_bytes = STAGES * STAGE_FLOATS * 4;   // 81920
    cudaFuncSetAttribute(wgemm128<true, true>,
                         cudaFuncAttributeMaxDynamicSharedMemorySize, smem_bytes);
    cudaFuncSetAttribute(wgemm128<false, false>,
                         cudaFuncAttributeMaxDynamicSharedMemorySize, smem_bytes);

    // prep: RN tf32 conversions (+ transposes)
    k_prep_q<<<(B_ * Q_ * H_) / 4 / 256, 256>>>(query);
    {
        dim3 g(H_ / 32, H_ / 32, 1);
        k_prep_W<<<g, dim3(32, 8)>>>(W);
    }
    {
        dim3 g(H_ / 32, D_ / 32, B_);
        k_prep_doc<<<g, dim3(32, 8)>>>(doc);
    }

    const float scale = 1.0f / 32.0f;   // 1/sqrt(H)

    // 1) q = query @ W + bias  (M=4096, N=1024, K=1024); output tf32-RN
    {
        dim3 g(H_ / TILE, (B_ * Q_) / TILE, 1);
        wgemm128<true, true><<<g, 256, smem_bytes>>>(
            p_query, p_WT, p_q, bias, H_, H_, 1.0f, 0, 0, 0);
    }
    // 2) scores = q @ doc^T * scale -> attn (fp32)
    {
        dim3 g(D_ / TILE, Q_ / TILE, B_);
        wgemm128<false, false><<<g, 256, smem_bytes>>>(
            p_q, p_doc, attn, nullptr, H_, D_, scale,
            (size_t)Q_ * H_, (size_t)D_ * H_, (size_t)Q_ * D_);
    }
    // 3) masked softmax in place; also emit tf32 copy for GEMM3
    softmax_kernel<<<B_ * Q_, 256>>>(attn, mask);
    // 4) retrieved = attn @ doc  (via docT, K-major)
    {
        dim3 g(H_ / TILE, Q_ / TILE, B_);
        wgemm128<false, false><<<g, 256, smem_bytes>>>(
            p_attn, p_docT, retrieved, nullptr, D_, H_, 1.0f,
            (size_t)Q_ * D_, (size_t)H_ * D_, (size_t)Q_ * H_);
    }
}

// round 4
// speedup vs baseline: 2.9443x; 1.1126x over previous
#include <cuda_runtime.h>
#include <math.h>
#include <stdint.h>

#define B_  8
#define Q_  512
#define D_  4096
#define H_  1024

#define STAGES 4
#define TILE   128
#define BK     16
#define STRD_A 20                        // A smem row stride (K-major rows)
#define STRD_BN 136                      // NN B smem row stride ([k][n])
#define STAGE_FLOATS 5120                // A(2560) + B(<=2560) per stage

// ---------------- scratch (static device memory; no allocs allowed) ----------
__device__ float g_q[(size_t)B_ * Q_ * H_];        // projected queries (fp32)

// ---------------- helpers ------------------------------------------------
__device__ __forceinline__ float tf32_rn(float x) {
    float r; asm("cvt.rna.tf32.f32 %0, %1;" : "=f"(r) : "f"(x)); return r;
}
__device__ __forceinline__ uint32_t tf32u(float x) {
    float r; asm("cvt.rna.tf32.f32 %0, %1;" : "=f"(r) : "f"(x));
    return __float_as_uint(r);
}
__device__ __forceinline__ void cp_async16(uint32_t dst, const void* src) {
    asm volatile("cp.async.cg.shared.global [%0], [%1], 16;" :: "r"(dst), "l"(src));
}
#define CP_COMMIT() asm volatile("cp.async.commit_group;" ::: "memory")
#define CP_WAIT(n)  asm volatile("cp.async.wait_group %0;" :: "n"(n) : "memory")

__device__ __forceinline__ uint32_t smem_u32(const void* p) {
    uint32_t a;
    asm("{ .reg .u64 t; cvta.to.shared.u64 t, %1; cvt.u32.u64 %0, t; }" : "=r"(a) : "l"(p));
    return a;
}

__device__ __forceinline__ void mma_tf32(float* c, const uint32_t* a, const uint32_t* b) {
    asm volatile(
        "mma.sync.aligned.m16n8k8.row.col.f32.tf32.tf32.f32 "
        "{%0,%1,%2,%3}, {%4,%5,%6,%7}, {%8,%9}, {%0,%1,%2,%3};"
        : "+f"(c[0]), "+f"(c[1]), "+f"(c[2]), "+f"(c[3])
        : "r"(a[0]), "r"(a[1]), "r"(a[2]), "r"(a[3]), "r"(b[0]), "r"(b[1]));
}

// ---------------- warp-MMA TF32 GEMM -----------------------------------------
// C[m][n] = alpha * sum_k A[m][k] * op(B) (+ bias[n])
//   A: [M,K] K-major rows, pitch lda.
//   B_KMAJOR=1: B is [N,K] K-major rows (op(B)=B[n][k]), pitch ldb.
//   B_KMAJOR=0: B is [K,N] rows of N (op(B)=B[k][n]),    pitch ldb.
// Inputs are fp32; fragments are RN-converted to tf32 in-register.
// grid: (N/128, M/128, batches), 256 threads.
template <bool B_KMAJOR, bool HAS_BIAS>
__global__ void __launch_bounds__(256, 2) wgemm128(
    const float* __restrict__ A, const float* __restrict__ Bm,
    float* __restrict__ C, const float* __restrict__ bias,
    int K, int lda, int ldb, int ldc, float alpha,
    size_t strideA, size_t strideB, size_t strideC)
{
    extern __shared__ float smf[];
    const uint32_t sbase = smem_u32(smf);

    const int tid  = threadIdx.x;
    const int lane = tid & 31;
    const int wid  = tid >> 5;
    const int row  = lane >> 2;      // 0..7
    const int tig  = lane & 3;       // 0..3
    const int warp_m = (wid & 3) * 32;
    const int warp_n = (wid >> 2) * 64;

    const size_t batch = blockIdx.z;
    const float* Ab = A + batch * strideA + (size_t)(blockIdx.y * TILE) * lda;
    const float* Bb;
    if (B_KMAJOR)
        Bb = Bm + batch * strideB + (size_t)(blockIdx.x * TILE) * ldb;
    else
        Bb = Bm + batch * strideB + blockIdx.x * TILE;

    // per-thread cp.async chunk ids
    const int c0 = tid, c1 = tid + 256;          // 0..511
    // A (and NT B) addressing: row-major K chunks
    const int ar0 = c0 >> 2, aq0 = c0 & 3;
    const int ar1 = c1 >> 2, aq1 = c1 & 3;
    // NN B addressing: [k][n] chunks
    const int bk0 = c0 >> 5, bn0 = (c0 & 31) * 4;
    const int bk1 = c1 >> 5, bn1 = (c1 & 31) * 4;

    float acc[2][8][4];
#pragma unroll
    for (int mt = 0; mt < 2; mt++)
#pragma unroll
        for (int nt = 0; nt < 8; nt++)
#pragma unroll
            for (int i = 0; i < 4; i++) acc[mt][nt][i] = 0.0f;

    const int NK = K / BK;

    // ---- stage loader ----
    auto load_stage = [&](int kb) {
        const int s = kb % STAGES;
        const uint32_t stA = sbase + s * STAGE_FLOATS * 4;
        const uint32_t stB = stA + TILE * STRD_A * 4;
        const float* gA = Ab + kb * BK;
        cp_async16(stA + (ar0 * STRD_A + aq0 * 4) * 4, gA + (size_t)ar0 * lda + aq0 * 4);
        cp_async16(stA + (ar1 * STRD_A + aq1 * 4) * 4, gA + (size_t)ar1 * lda + aq1 * 4);
        if (B_KMAJOR) {
            const float* gB = Bb + kb * BK;
            cp_async16(stB + (ar0 * STRD_A + aq0 * 4) * 4, gB + (size_t)ar0 * ldb + aq0 * 4);
            cp_async16(stB + (ar1 * STRD_A + aq1 * 4) * 4, gB + (size_t)ar1 * ldb + aq1 * 4);
        } else {
            const float* gB = Bb + (size_t)(kb * BK) * ldb;
            cp_async16(stB + (bk0 * STRD_BN + bn0) * 4, gB + (size_t)bk0 * ldb + bn0);
            cp_async16(stB + (bk1 * STRD_BN + bn1) * 4, gB + (size_t)bk1 * ldb + bn1);
        }
    };

    // ---- prologue: fill STAGES-1 stages ----
#pragma unroll
    for (int s = 0; s < STAGES - 1; s++) {
        load_stage(s);
        CP_COMMIT();
    }

    for (int kb = 0; kb < NK; kb++) {
        CP_WAIT(STAGES - 2);
        __syncthreads();

        const int kn = kb + STAGES - 1;
        if (kn < NK) load_stage(kn);
        CP_COMMIT();

        // ---- compute current stage ----
        const float* As = smf + (kb % STAGES) * STAGE_FLOATS;
        const float* Bs = As + TILE * STRD_A;
#pragma unroll
        for (int kk = 0; kk < BK; kk += 8) {
            uint32_t a[2][4], b[8][2];
#pragma unroll
            for (int mt = 0; mt < 2; mt++) {
                const float* ap = As + (warp_m + mt * 16 + row) * STRD_A + kk + tig;
                a[mt][0] = tf32u(ap[0]);
                a[mt][1] = tf32u(ap[8 * STRD_A]);
                a[mt][2] = tf32u(ap[4]);
                a[mt][3] = tf32u(ap[8 * STRD_A + 4]);
            }
#pragma unroll
            for (int nt = 0; nt < 8; nt++) {
                if (B_KMAJOR) {
                    const float* bp = Bs + (warp_n + nt * 8 + row) * STRD_A + kk + tig;
                    b[nt][0] = tf32u(bp[0]);
                    b[nt][1] = tf32u(bp[4]);
                } else {
                    const float* bp = Bs + (size_t)(kk + tig) * STRD_BN + warp_n + nt * 8 + row;
                    b[nt][0] = tf32u(bp[0]);
                    b[nt][1] = tf32u(bp[4 * STRD_BN]);
                }
            }
#pragma unroll
            for (int mt = 0; mt < 2; mt++)
#pragma unroll
                for (int nt = 0; nt < 8; nt++)
                    mma_tf32(acc[mt][nt], a[mt], b[nt]);
        }
        __syncthreads();
    }

    // ---- epilogue ----
    float* Cb = C + batch * strideC;
#pragma unroll
    for (int mt = 0; mt < 2; mt++) {
        const int r0 = blockIdx.y * TILE + warp_m + mt * 16 + row;
#pragma unroll
        for (int nt = 0; nt < 8; nt++) {
            const int col = blockIdx.x * TILE + warp_n + nt * 8 + 2 * tig;
            float bx = 0.f, by = 0.f;
            if (HAS_BIAS) { bx = __ldg(bias + col); by = __ldg(bias + col + 1); }
            float2 v0, v1;
            v0.x = acc[mt][nt][0] * alpha + bx;
            v0.y = acc[mt][nt][1] * alpha + by;
            v1.x = acc[mt][nt][2] * alpha + bx;
            v1.y = acc[mt][nt][3] * alpha + by;
            *(float2*)(Cb + (size_t)r0 * ldc + col) = v0;
            *(float2*)(Cb + (size_t)(r0 + 8) * ldc + col) = v1;
        }
    }
}

// ---------------- masked softmax over D (in place) ---------------------------
__global__ void __launch_bounds__(256) softmax_kernel(
    float* __restrict__ attn, const int* __restrict__ mask)
{
    const int row = blockIdx.x;            // b*Q_ + q
    const int b = row / Q_;
    const int* mrow = mask + (size_t)b * D_;
    float* s = attn + (size_t)row * D_;
    const int tid = threadIdx.x;

    float v[16];
    int mk[16];
    float mx = -INFINITY;
#pragma unroll
    for (int i = 0; i < 16; i++) {
        int d = tid + i * 256;
        mk[i] = mrow[d];
        float x = s[d];
        v[i] = (mk[i] != 0) ? x : -INFINITY;
        mx = fmaxf(mx, v[i]);
    }

    __shared__ float red[8];
#pragma unroll
    for (int off = 16; off > 0; off >>= 1)
        mx = fmaxf(mx, __shfl_xor_sync(0xffffffffu, mx, off));
    if ((tid & 31) == 0) red[tid >> 5] = mx;
    __syncthreads();
    if (tid < 32) {
        float m2 = (tid < 8) ? red[tid] : -INFINITY;
#pragma unroll
        for (int off = 4; off > 0; off >>= 1)
            m2 = fmaxf(m2, __shfl_xor_sync(0xffffffffu, m2, off));
        if (tid == 0) red[0] = m2;
    }
    __syncthreads();
    mx = red[0];

    float sum = 0.0f;
#pragma unroll
    for (int i = 0; i < 16; i++) {
        float e = (mk[i] != 0) ? expf(v[i] - mx) : 0.0f;
        v[i] = e;
        sum += e;
    }
#pragma unroll
    for (int off = 16; off > 0; off >>= 1)
        sum += __shfl_xor_sync(0xffffffffu, sum, off);
    __syncthreads();
    if ((tid & 31) == 0) red[tid >> 5] = sum;
    __syncthreads();
    if (tid < 32) {
        float s2 = (tid < 8) ? red[tid] : 0.0f;
#pragma unroll
        for (int off = 4; off > 0; off >>= 1)
            s2 += __shfl_xor_sync(0xffffffffu, s2, off);
        if (tid == 0) red[0] = s2;
    }
    __syncthreads();
    const float inv = 1.0f / red[0];

#pragma unroll
    for (int i = 0; i < 16; i++) {
        int d = tid + i * 256;
        s[d] = v[i] * inv;
    }
}

// ---------------- launch -----------------------------------------------------
extern "C" void kernel_launch(void* const* d_in, const int* in_sizes, int n_in,
                              void* d_out, int out_size)
{
    const float* query = (const float*)d_in[0];   // [B,Q,H]
    const float* doc   = (const float*)d_in[1];   // [B,D,H]
    const int*   mask  = (const int*)d_in[2];     // [B,D]
    const float* W     = (const float*)d_in[3];   // [H,H]
    const float* bias  = (const float*)d_in[4];   // [H]

    float* out = (float*)d_out;
    float* retrieved = out;                               // [B,Q,H]
    float* attn = out + (size_t)B_ * Q_ * H_;             // [B,Q,D]

    float* p_q;
    cudaGetSymbolAddress((void**)&p_q, g_q);

    const int smem_bytes = STAGES * STAGE_FLOATS * 4;   // 81920
    cudaFuncSetAttribute(wgemm128<false, true>,
                         cudaFuncAttributeMaxDynamicSharedMemorySize, smem_bytes);
    cudaFuncSetAttribute(wgemm128<true, false>,
                         cudaFuncAttributeMaxDynamicSharedMemorySize, smem_bytes);
    cudaFuncSetAttribute(wgemm128<false, false>,
                         cudaFuncAttributeMaxDynamicSharedMemorySize, smem_bytes);

    const float scale = 1.0f / 32.0f;   // 1/sqrt(H)

    // 1) q = query @ W + bias  (M=B*Q=4096, N=H, K=H); B = W [K,N] (NN)
    {
        dim3 g(H_ / TILE, (B_ * Q_) / TILE, 1);
        wgemm128<false, true><<<g, 256, smem_bytes>>>(
            query, W, p_q, bias, H_, H_, H_, H_, 1.0f, 0, 0, 0);
    }
    // 2) scores = q @ doc^T * scale -> attn; B = doc [N,K] (NT)
    {
        dim3 g(D_ / TILE, Q_ / TILE, B_);
        wgemm128<true, false><<<g, 256, smem_bytes>>>(
            p_q, doc, attn, nullptr, H_, H_, H_, D_, scale,
            (size_t)Q_ * H_, (size_t)D_ * H_, (size_t)Q_ * D_);
    }
    // 3) masked softmax in place over D
    softmax_kernel<<<B_ * Q_, 256>>>(attn, mask);
    // 4) retrieved = attn @ doc; B = doc [K,N] (NN), K = D
    {
        dim3 g(H_ / TILE, Q_ / TILE, B_);
        wgemm128<false, false><<<g, 256, smem_bytes>>>(
            attn, doc, retrieved, nullptr, D_, D_, H_, H_, 1.0f,
            (size_t)Q_ * D_, (size_t)D_ * H_, (size_t)Q_ * H_);
    }
}